// round 9
// baseline (speedup 1.0000x reference)
#include <cuda_runtime.h>

#define ETA 1e-5f
#define FULLMASK 0xffffffffu

static const int D    = 1024;
static const int DA   = 1023;   // a = x[:-1]
static const int M2   = 512;
static const int NMAX = 20000;
static const int L    = 32;                 // chunk length
static const int NCMAX = NMAX / L;          // 625

// Static device scratch (no runtime allocation allowed)
__device__ float g_AtT[(size_t)NMAX * D];        // row i = x_i (contiguous)
__device__ float g_last[NMAX];                   // x_i[1023] densely packed
__device__ float g_S[(size_t)NCMAX * L * L];     // per-chunk a-Gram: S[c][j][i] = a_j . a_i
__device__ float g_Tsq[(size_t)M2 * NMAX];       // Tsq[r][i] = t_i[r]^2
__device__ float g_T2[NMAX];                     // ||t_i||^2

// ---------------------------------------------------------------------------
// V8: 32 floats as 8 named float4 members (no indexable array).
// Lane-interleaved ownership: lane l owns float4s {l, l+32, ..., l+224} of a
// row -> coalesced LDG.128 (4 lines/instr).
// ---------------------------------------------------------------------------
struct V8 { float4 a, b, c, d, e, f, g, h; };

#define V8_FOREACH(M) M(a) M(b) M(c) M(d) M(e) M(f) M(g) M(h)

__device__ __forceinline__ void ldv8(V8& v, int row, int lane, bool mask_last) {
    const float4* q = reinterpret_cast<const float4*>(&g_AtT[(size_t)row * D]) + lane;
    v.a = q[0];   v.b = q[32];  v.c = q[64];  v.d = q[96];
    v.e = q[128]; v.f = q[160]; v.g = q[192]; v.h = q[224];
    if (mask_last && lane == 31) v.h.w = 0.f;   // element 1023 not part of a
}

__device__ __forceinline__ float dot32(const V8& u, const V8& v) {
    float s0, s1, s2, s3;
    s0 = u.a.x * v.a.x; s1 = u.a.y * v.a.y; s2 = u.a.z * v.a.z; s3 = u.a.w * v.a.w;
#define DOT_M(m) \
    s0 = fmaf(u.m.x, v.m.x, s0); s1 = fmaf(u.m.y, v.m.y, s1); \
    s2 = fmaf(u.m.z, v.m.z, s2); s3 = fmaf(u.m.w, v.m.w, s3);
    DOT_M(b) DOT_M(c) DOT_M(d) DOT_M(e) DOT_M(f) DOT_M(g) DOT_M(h)
#undef DOT_M
    return (s0 + s1) + (s2 + s3);
}

__device__ __forceinline__ void fma32(V8& G, float t, const V8& x) {
#define FMA_M(m) \
    G.m.x = fmaf(t, x.m.x, G.m.x); G.m.y = fmaf(t, x.m.y, G.m.y); \
    G.m.z = fmaf(t, x.m.z, G.m.z); G.m.w = fmaf(t, x.m.w, G.m.w);
    V8_FOREACH(FMA_M)
#undef FMA_M
}

__device__ __forceinline__ void zero32(V8& G) {
    float4 z = make_float4(0.f, 0.f, 0.f, 0.f);
#define Z_M(m) G.m = z;
    V8_FOREACH(Z_M)
#undef Z_M
}

__device__ __forceinline__ float warp_sum(float s) {
    #pragma unroll
    for (int o = 16; o; o >>= 1) s += __shfl_xor_sync(FULLMASK, s, o);
    return s;
}

// ---------------------------------------------------------------------------
// Kernel 0: transpose At (D x N) -> g_AtT (N x D); also pack column 1023.
// ---------------------------------------------------------------------------
__global__ void k_transpose(const float* __restrict__ At, int N) {
    __shared__ float tile[32][33];
    int i0 = blockIdx.x * 32;           // N dim
    int r0 = blockIdx.y * 32;           // D dim
    int tx = threadIdx.x, ty = threadIdx.y;   // blockDim (32, 8)
    #pragma unroll
    for (int k = 0; k < 32; k += 8) {
        int r = r0 + ty + k, i = i0 + tx;
        if (i < N) tile[ty + k][tx] = At[(size_t)r * N + i];
    }
    __syncthreads();
    #pragma unroll
    for (int k = 0; k < 32; k += 8) {
        int i = i0 + ty + k, r = r0 + tx;
        if (i < N) {
            float v = tile[tx][ty + k];
            g_AtT[(size_t)i * D + r] = v;
            if (r == D - 1) g_last[i] = v;
        }
    }
}

// ---------------------------------------------------------------------------
// Kernel 0b: per-chunk a-Gram. One CTA (1024 thr) per chunk.
// S[c][j][i] = sum_{k<1023} x_{c*32+j}[k] * x_{c*32+i}[k]
// ---------------------------------------------------------------------------
__global__ void __launch_bounds__(1024) k_gram(int NC) {
    __shared__ float tile[64][33];      // padded
    int c = blockIdx.x;
    if (c >= NC) return;
    int tid = threadIdx.x;
    int i = tid & 31, j = tid >> 5;
    int base = c * L;
    float s = 0.f;
    for (int k0 = 0; k0 < D; k0 += 64) {
        __syncthreads();
        #pragma unroll
        for (int e = tid; e < 32 * 64; e += 1024) {
            int row = e >> 6, kk = e & 63;
            tile[kk][row] = g_AtT[(size_t)(base + row) * D + k0 + kk];
        }
        __syncthreads();
        #pragma unroll
        for (int kk = 0; kk < 64; kk++)
            s = fmaf(tile[kk][j], tile[kk][i], s);
    }
    // remove k = 1023 term -> a-gram
    float lj = g_last[base + j];
    float li = g_last[base + i];
    g_S[(size_t)c * (L * L) + j * L + i] = s - lj * li;
}

// ---------------------------------------------------------------------------
// Kernel 1: W2 path, chunked linear recurrence. 512 warps; warp r owns g_W2
// row r in registers. Phase-1 partials staged in padded smem (low reg peak).
// ---------------------------------------------------------------------------
__global__ void __launch_bounds__(128) k_w2(const float* __restrict__ W2init, int N) {
    __shared__ float sm_P[4][32 * 33];  // per-warp padded partial tile (16.9KB)
    int wix  = (threadIdx.x >> 5);                      // warp in CTA (0..3)
    int r    = (blockIdx.x * 128 + threadIdx.x) >> 5;   // 0..511
    int lane = threadIdx.x & 31;
    int NC   = N / L;
    float* myP = sm_P[wix];

    V8 G; zero32(G);

    // qinit = W2init[r] . a_0   (step 0 uses W2_init directly).
    float qinit;
    {
        V8 x; ldv8(x, 0, lane, true);
        const float* wrow = W2init + (size_t)r * DA;
        float s0 = 0.f, s1 = 0.f, s2 = 0.f, s3 = 0.f;
        int eo;
#define QD(m, kk) \
        eo = (kk * 32 + lane) * 4; \
        s0 = fmaf(wrow[eo + 0], x.m.x, s0); \
        s1 = fmaf(wrow[eo + 1], x.m.y, s1); \
        s2 = fmaf(wrow[eo + 2], x.m.z, s2); \
        s3 = fmaf((eo + 3 < DA) ? wrow[eo + 3] : 0.f, x.m.w, s3);
        QD(a,0) QD(b,1) QD(c,2) QD(d,3) QD(e,4) QD(f,5) QD(g,6) QD(h,7)
#undef QD
        qinit = warp_sum((s0 + s1) + (s2 + s3));
    }

    for (int c = 0; c < NC; c++) {
        int base = c * L;

        // ---- Phase 1: partial of (G . a_{base+i}) -> smem [i][lane]
        #pragma unroll
        for (int i = 0; i < 32; i++) {
            V8 x; ldv8(x, base + i, lane, true);
            myP[i * 33 + lane] = dot32(G, x);
        }
        __syncwarp();

        // ---- Load S column (only live through the solve; latency hidden
        // under the row-sum below). lane i needs S[j][i] for all j.
        float Scol[32];
        {
            const float* Sc = &g_S[(size_t)c * (L * L)];
            #pragma unroll
            for (int j = 0; j < 32; j++) Scol[j] = Sc[j * 32 + lane];
        }

        // ---- Row-sum: lane i sums its padded row -> q_i. Banks (i+k)%32:
        // conflict-free.
        float q;
        {
            float t0 = 0.f, t1 = 0.f, t2r = 0.f, t3 = 0.f;
            #pragma unroll
            for (int k = 0; k < 32; k += 4) {
                t0 += myP[lane * 33 + k + 0];
                t1 += myP[lane * 33 + k + 1];
                t2r += myP[lane * 33 + k + 2];
                t3 += myP[lane * 33 + k + 3];
            }
            q = (t0 + t1) + (t2r + t3);
        }

        // ---- Phase 2: triangular solve
        // t_i = -ETA*q_i - 2*ETA*sum_{j<i} S[j][i]*t_j   (lane i -> t_i)
        bool special = (c == 0) && (lane == 0);
        float acc = 0.f, tfin = 0.f;
        #pragma unroll
        for (int j = 0; j < 32; j++) {
            float cand = fmaf(-2.f * ETA, acc, -ETA * q);
            if (special) cand = qinit;
            float tj = __shfl_sync(FULLMASK, cand, j);
            if (lane == j) tfin = cand;
            acc = fmaf(Scol[j], tj, acc);
        }

        g_Tsq[(size_t)r * N + base + lane] = tfin * tfin;

        // ---- Phase 3: G += sum_i 2 t_i a_i^T   (rows L1-resident)
        float t2 = 2.f * tfin;
        #pragma unroll 4
        for (int i = 0; i < 32; i++) {
            float ti2 = __shfl_sync(FULLMASK, t2, i);
            V8 x; ldv8(x, base + i, lane, true);
            fma32(G, ti2, x);
        }
    }
}

// ---------------------------------------------------------------------------
// Kernel 1b: T2[i] = sum_r Tsq[r][i]
// ---------------------------------------------------------------------------
__global__ void k_reduce(int N) {
    int i = blockIdx.x * blockDim.x + threadIdx.x;
    if (i >= N) return;
    float s = 0.f;
    #pragma unroll 8
    for (int r = 0; r < M2; r++) s += g_Tsq[(size_t)r * N + i];
    g_T2[i] = s;
}

// ---------------------------------------------------------------------------
// Kernel 2: w1 scalar scan, chunked. One CTA of 1024 threads.
// ---------------------------------------------------------------------------
__global__ void __launch_bounds__(1024) k_w1(const float* __restrict__ w1init,
                                             const float* __restrict__ b,
                                             float* __restrict__ preds, int N) {
    __shared__ float sm_g[1024];
    __shared__ float sm_S[1024];        // this chunk's S tile (4KB)
    __shared__ float sm_p[32];
    __shared__ float sm_c[32];
    int tid  = threadIdx.x;
    int w    = tid >> 5, lane = tid & 31;
    int NC   = N / L;

    sm_g[tid] = 0.f;
    __syncthreads();

    for (int c = 0; c < NC; c++) {
        int base = c * L;

        // ---- Stage S tile to shared (coalesced, overlaps phase A)
        sm_S[tid] = g_S[(size_t)c * (L * L) + tid];

        // ---- Phase A: p_w = x_{base+w} . g_s   (chunk 0, warp 0: w1init . x_0)
        {
            const float* xrow = &g_AtT[(size_t)(base + w) * D];
            float s = 0.f;
            if (c == 0 && w == 0) {
                #pragma unroll 8
                for (int k = 0; k < 32; k++)
                    s = fmaf(w1init[lane + 32 * k], xrow[lane + 32 * k], s);
            } else {
                #pragma unroll 8
                for (int k = 0; k < 32; k++)
                    s = fmaf(sm_g[lane + 32 * k], xrow[lane + 32 * k], s);
            }
            s = warp_sum(s);
            if (lane == 0) sm_p[w] = s;
        }
        __syncthreads();

        // ---- Phase B: warp 0 solves the 32-step scalar recurrence
        if (w == 0) {
            float p   = sm_p[lane];
            float li  = g_last[base + lane];     // one cache line
            float T2i = g_T2[base + lane];
            float bi  = b[base + lane];
            bool special = (c == 0) && (lane == 0);
            float acc = 0.f, scal_f = 0.f, c_f = 0.f;
            #pragma unroll
            for (int j = 0; j < 32; j++) {
                float scal = fmaf(-ETA, p + acc, T2i);
                if (special) scal = p + T2i;       // step 0: w1_init . x_0 + T2_0
                float cc = 2.f * (scal - bi);
                float lj = __shfl_sync(FULLMASK, li, j);
                float cj = __shfl_sync(FULLMASK, cc, j);
                if (lane == j) { scal_f = scal; c_f = cc; }
                float Sji = fmaf(lj, li, sm_S[j * 32 + lane]); // x-gram = a-gram + l_j*l_i
                acc = fmaf(Sji, cj, acc);
            }
            preds[base + lane] = scal_f;
            sm_c[lane] = c_f;
        }
        __syncthreads();

        // ---- Phase C: g[t] += sum_i c_i * x_{base+i}[t]
        {
            float gt = sm_g[tid];
            #pragma unroll
            for (int i = 0; i < 32; i++)
                gt = fmaf(sm_c[i], g_AtT[(size_t)(base + i) * D + tid], gt);
            sm_g[tid] = gt;
        }
        __syncthreads();
    }
}

// ---------------------------------------------------------------------------
// Kernel 3: copy b into second half of output
// ---------------------------------------------------------------------------
__global__ void k_copyb(const float* __restrict__ b, float* __restrict__ out, int N) {
    int i = blockIdx.x * blockDim.x + threadIdx.x;
    if (i < N) out[i] = b[i];
}

// ---------------------------------------------------------------------------
extern "C" void kernel_launch(void* const* d_in, const int* in_sizes, int n_in,
                              void* d_out, int out_size) {
    const float* At = (const float*)d_in[0];
    const float* b  = (const float*)d_in[1];
    const float* w1 = (const float*)d_in[2];
    const float* W2 = (const float*)d_in[3];
    int N = in_sizes[1];                 // 20000
    int NC = N / L;
    float* out = (float*)d_out;

    dim3 tb(32, 8);
    dim3 tg((N + 31) / 32, D / 32);
    k_transpose<<<tg, tb>>>(At, N);

    k_gram<<<NC, 1024>>>(NC);

    k_w2<<<128, 128>>>(W2, N);           // 512 warps = 512 rows

    k_reduce<<<(N + 255) / 256, 256>>>(N);

    k_w1<<<1, 1024>>>(w1, b, out, N);

    if (out_size >= 2 * N)
        k_copyb<<<(N + 255) / 256, 256>>>(b, out + N, N);
}

// round 10
// speedup vs baseline: 2.5344x; 2.5344x over previous
#include <cuda_runtime.h>

#define ETA 1e-5f
#define FULLMASK 0xffffffffu

static const int D    = 1024;
static const int DA   = 1023;   // a = x[:-1]
static const int M2   = 512;
static const int NMAX = 20000;
static const int L    = 32;                 // chunk length
static const int NCMAX = NMAX / L;          // 625

// Static device scratch (no runtime allocation allowed)
__device__ float g_AtT[(size_t)NMAX * D];        // row i = x_i (contiguous)
__device__ float g_last[NMAX];                   // x_i[1023] densely packed
__device__ float g_S[(size_t)NCMAX * L * L];     // per-chunk a-Gram: S[c][j][i] = a_j . a_i
__device__ float g_Tsq[(size_t)M2 * NMAX];       // Tsq[r][i] = t_i[r]^2
__device__ float g_T2[NMAX];                     // ||t_i||^2
__device__ unsigned long long g_dummy;

// ---------------------------------------------------------------------------
// V8: 32 floats as 8 named float4 members (no indexable array).
// Lane-interleaved ownership: lane l owns float4s {l, l+32, ..., l+224}.
// ---------------------------------------------------------------------------
struct V8 { float4 a, b, c, d, e, f, g, h; };

#define V8_FOREACH(M) M(a) M(b) M(c) M(d) M(e) M(f) M(g) M(h)

__device__ __forceinline__ void ldv8g(V8& v, int row, int lane, bool mask_last) {
    const float4* q = reinterpret_cast<const float4*>(&g_AtT[(size_t)row * D]) + lane;
    v.a = q[0];   v.b = q[32];  v.c = q[64];  v.d = q[96];
    v.e = q[128]; v.f = q[160]; v.g = q[192]; v.h = q[224];
    if (mask_last && lane == 31) v.h.w = 0.f;
}

// Shared-memory variant: row already masked in the tile.
__device__ __forceinline__ void ldv8s(V8& v, const float* smrow, int lane) {
    const float4* q = reinterpret_cast<const float4*>(smrow) + lane;
    v.a = q[0];   v.b = q[32];  v.c = q[64];  v.d = q[96];
    v.e = q[128]; v.f = q[160]; v.g = q[192]; v.h = q[224];
}

__device__ __forceinline__ float dot32(const V8& u, const V8& v) {
    float s0, s1, s2, s3;
    s0 = u.a.x * v.a.x; s1 = u.a.y * v.a.y; s2 = u.a.z * v.a.z; s3 = u.a.w * v.a.w;
#define DOT_M(m) \
    s0 = fmaf(u.m.x, v.m.x, s0); s1 = fmaf(u.m.y, v.m.y, s1); \
    s2 = fmaf(u.m.z, v.m.z, s2); s3 = fmaf(u.m.w, v.m.w, s3);
    DOT_M(b) DOT_M(c) DOT_M(d) DOT_M(e) DOT_M(f) DOT_M(g) DOT_M(h)
#undef DOT_M
    return (s0 + s1) + (s2 + s3);
}

__device__ __forceinline__ void fma32(V8& G, float t, const V8& x) {
#define FMA_M(m) \
    G.m.x = fmaf(t, x.m.x, G.m.x); G.m.y = fmaf(t, x.m.y, G.m.y); \
    G.m.z = fmaf(t, x.m.z, G.m.z); G.m.w = fmaf(t, x.m.w, G.m.w);
    V8_FOREACH(FMA_M)
#undef FMA_M
}

__device__ __forceinline__ void zero32(V8& G) {
    float4 z = make_float4(0.f, 0.f, 0.f, 0.f);
#define Z_M(m) G.m = z;
    V8_FOREACH(Z_M)
#undef Z_M
}

__device__ __forceinline__ float warp_sum(float s) {
    #pragma unroll
    for (int o = 16; o; o >>= 1) s += __shfl_xor_sync(FULLMASK, s, o);
    return s;
}

// Batched transpose-reduce: lane l enters with P[v] = its partial of reduction
// v, exits with the full sum of reduction l. 31 shfl total, critical path 5.
__device__ __forceinline__ float colsum32(float (&P)[32], int lane) {
    #pragma unroll
    for (int s = 16; s >= 1; s >>= 1) {
        bool hi = (lane & s) != 0;
        #pragma unroll
        for (int v = 0; v < s; v++) {
            float send = hi ? P[v] : P[v + s];
            float recv = __shfl_xor_sync(FULLMASK, send, s);
            float keep = hi ? P[v + s] : P[v];
            P[v] = keep + recv;
        }
    }
    return P[0];
}

// ---------------------------------------------------------------------------
// Kernel 0: transpose At (D x N) -> g_AtT; also pack column 1023.
// ---------------------------------------------------------------------------
__global__ void k_transpose(const float* __restrict__ At, int N) {
    __shared__ float tile[32][33];
    int i0 = blockIdx.x * 32;
    int r0 = blockIdx.y * 32;
    int tx = threadIdx.x, ty = threadIdx.y;   // blockDim (32, 8)
    #pragma unroll
    for (int k = 0; k < 32; k += 8) {
        int r = r0 + ty + k, i = i0 + tx;
        if (i < N) tile[ty + k][tx] = At[(size_t)r * N + i];
    }
    __syncthreads();
    #pragma unroll
    for (int k = 0; k < 32; k += 8) {
        int i = i0 + ty + k, r = r0 + tx;
        if (i < N) {
            float v = tile[tx][ty + k];
            g_AtT[(size_t)i * D + r] = v;
            if (r == D - 1) g_last[i] = v;
        }
    }
}

// ---------------------------------------------------------------------------
// Kernel 0b: per-chunk a-Gram. One CTA (1024 thr) per chunk.
// ---------------------------------------------------------------------------
__global__ void __launch_bounds__(1024) k_gram(int NC) {
    __shared__ float tile[64][33];
    int c = blockIdx.x;
    if (c >= NC) return;
    int tid = threadIdx.x;
    int i = tid & 31, j = tid >> 5;
    int base = c * L;
    float s = 0.f;
    for (int k0 = 0; k0 < D; k0 += 64) {
        __syncthreads();
        #pragma unroll
        for (int e = tid; e < 32 * 64; e += 1024) {
            int row = e >> 6, kk = e & 63;
            tile[kk][row] = g_AtT[(size_t)(base + row) * D + k0 + kk];
        }
        __syncthreads();
        #pragma unroll
        for (int kk = 0; kk < 64; kk++)
            s = fmaf(tile[kk][j], tile[kk][i], s);
    }
    float lj = g_last[base + j];
    float li = g_last[base + i];
    g_S[(size_t)c * (L * L) + j * L + i] = s - lj * li;
}

// ---------------------------------------------------------------------------
// Dummy kernel: shifts the ncu capture slot onto k_w2 (it was landing on the
// launch right after k_w2). Deterministic no-op.
// ---------------------------------------------------------------------------
__global__ void k_dummy() { g_dummy = 0ull; }

// ---------------------------------------------------------------------------
// Kernel 1: W2 path, chunked. 512 warps; warp r owns g_W2 row r in registers.
// Chunk X tile staged once in 128KB dynamic smem; phases read LDS
// (deterministic 29-cyc, conflict-free, no L1 miss churn).
// ---------------------------------------------------------------------------
__global__ void __launch_bounds__(128) k_w2(const float* __restrict__ W2init, int N) {
    extern __shared__ float sm_x[];                     // 32 rows x 1024 floats
    int r    = (blockIdx.x * 128 + threadIdx.x) >> 5;   // 0..511
    int lane = threadIdx.x & 31;
    int tid  = threadIdx.x;
    int NC   = N / L;

    V8 G; zero32(G);

    // qinit = W2init[r] . a_0   (step 0 uses W2_init directly)
    float qinit;
    {
        V8 x; ldv8g(x, 0, lane, true);
        const float* wrow = W2init + (size_t)r * DA;
        float s0 = 0.f, s1 = 0.f, s2 = 0.f, s3 = 0.f;
        int eo;
#define QD(m, kk) \
        eo = (kk * 32 + lane) * 4; \
        s0 = fmaf(wrow[eo + 0], x.m.x, s0); \
        s1 = fmaf(wrow[eo + 1], x.m.y, s1); \
        s2 = fmaf(wrow[eo + 2], x.m.z, s2); \
        s3 = fmaf((eo + 3 < DA) ? wrow[eo + 3] : 0.f, x.m.w, s3);
        QD(a,0) QD(b,1) QD(c,2) QD(d,3) QD(e,4) QD(f,5) QD(g,6) QD(h,7)
#undef QD
        qinit = warp_sum((s0 + s1) + (s2 + s3));
    }

    for (int c = 0; c < NC; c++) {
        int base = c * L;

        // ---- Cooperative tile load: 32 rows x 1024 floats, coalesced.
        {
            const float4* src = reinterpret_cast<const float4*>(&g_AtT[(size_t)base * D]);
            float4* dst = reinterpret_cast<float4*>(sm_x);
            #pragma unroll
            for (int e = 0; e < 64; e++)
                dst[tid + 128 * e] = src[tid + 128 * e];
        }
        __syncthreads();
        if (tid < 32) sm_x[tid * D + (D - 1)] = 0.f;    // mask element 1023
        __syncthreads();

        // ---- Prefetch S column (global; hidden under phase-1 FMAs).
        float Scol[32];
        {
            const float* Sc = &g_S[(size_t)c * (L * L)];
            #pragma unroll
            for (int j = 0; j < 32; j++) Scol[j] = Sc[j * 32 + lane];
        }

        // ---- Phase 1: P[i] = lane-partial of (G . a_{base+i})
        float P[32];
        #pragma unroll
        for (int i = 0; i < 32; i++) {
            V8 x; ldv8s(x, sm_x + i * D, lane);
            P[i] = dot32(G, x);
        }
        float q = colsum32(P, lane);        // lane i -> q_i

        // ---- Phase 2: triangular solve
        // t_i = -ETA*q_i - 2*ETA*sum_{j<i} S[j][i]*t_j
        bool special = (c == 0) && (lane == 0);
        float acc = 0.f, tfin = 0.f;
        #pragma unroll
        for (int j = 0; j < 32; j++) {
            float cand = fmaf(-2.f * ETA, acc, -ETA * q);
            if (special) cand = qinit;
            float tj = __shfl_sync(FULLMASK, cand, j);
            if (lane == j) tfin = cand;
            acc = fmaf(Scol[j], tj, acc);
        }

        g_Tsq[(size_t)r * N + base + lane] = tfin * tfin;

        // ---- Phase 3: G += sum_i 2 t_i a_i^T  (from smem)
        float t2 = 2.f * tfin;
        #pragma unroll 4
        for (int i = 0; i < 32; i++) {
            float ti2 = __shfl_sync(FULLMASK, t2, i);
            V8 x; ldv8s(x, sm_x + i * D, lane);
            fma32(G, ti2, x);
        }
        __syncthreads();    // tile reuse barrier before next chunk's load
    }
}

// ---------------------------------------------------------------------------
// Kernel 1b: T2[i] = sum_r Tsq[r][i]
// ---------------------------------------------------------------------------
__global__ void k_reduce(int N) {
    int i = blockIdx.x * blockDim.x + threadIdx.x;
    if (i >= N) return;
    float s = 0.f;
    #pragma unroll 8
    for (int r = 0; r < M2; r++) s += g_Tsq[(size_t)r * N + i];
    g_T2[i] = s;
}

// ---------------------------------------------------------------------------
// Kernel 2: w1 scalar scan, chunked. One CTA of 1024 threads.
// ---------------------------------------------------------------------------
__global__ void __launch_bounds__(1024) k_w1(const float* __restrict__ w1init,
                                             const float* __restrict__ b,
                                             float* __restrict__ preds, int N) {
    __shared__ float sm_g[1024];
    __shared__ float sm_S[1024];
    __shared__ float sm_p[32];
    __shared__ float sm_c[32];
    int tid  = threadIdx.x;
    int w    = tid >> 5, lane = tid & 31;
    int NC   = N / L;

    sm_g[tid] = 0.f;
    __syncthreads();

    for (int c = 0; c < NC; c++) {
        int base = c * L;

        sm_S[tid] = g_S[(size_t)c * (L * L) + tid];

        // ---- Phase A: p_w = x_{base+w} . g_s
        {
            const float* xrow = &g_AtT[(size_t)(base + w) * D];
            float s = 0.f;
            if (c == 0 && w == 0) {
                #pragma unroll 8
                for (int k = 0; k < 32; k++)
                    s = fmaf(w1init[lane + 32 * k], xrow[lane + 32 * k], s);
            } else {
                #pragma unroll 8
                for (int k = 0; k < 32; k++)
                    s = fmaf(sm_g[lane + 32 * k], xrow[lane + 32 * k], s);
            }
            s = warp_sum(s);
            if (lane == 0) sm_p[w] = s;
        }
        __syncthreads();

        // ---- Phase B: warp 0 solves the 32-step scalar recurrence
        if (w == 0) {
            float p   = sm_p[lane];
            float li  = g_last[base + lane];
            float T2i = g_T2[base + lane];
            float bi  = b[base + lane];
            bool special = (c == 0) && (lane == 0);
            float acc = 0.f, scal_f = 0.f, c_f = 0.f;
            #pragma unroll
            for (int j = 0; j < 32; j++) {
                float scal = fmaf(-ETA, p + acc, T2i);
                if (special) scal = p + T2i;
                float cc = 2.f * (scal - bi);
                float lj = __shfl_sync(FULLMASK, li, j);
                float cj = __shfl_sync(FULLMASK, cc, j);
                if (lane == j) { scal_f = scal; c_f = cc; }
                float Sji = fmaf(lj, li, sm_S[j * 32 + lane]);
                acc = fmaf(Sji, cj, acc);
            }
            preds[base + lane] = scal_f;
            sm_c[lane] = c_f;
        }
        __syncthreads();

        // ---- Phase C: g[t] += sum_i c_i * x_{base+i}[t]
        {
            float gt = sm_g[tid];
            #pragma unroll
            for (int i = 0; i < 32; i++)
                gt = fmaf(sm_c[i], g_AtT[(size_t)(base + i) * D + tid], gt);
            sm_g[tid] = gt;
        }
        __syncthreads();
    }
}

// ---------------------------------------------------------------------------
// Kernel 3: copy b into second half of output
// ---------------------------------------------------------------------------
__global__ void k_copyb(const float* __restrict__ b, float* __restrict__ out, int N) {
    int i = blockIdx.x * blockDim.x + threadIdx.x;
    if (i < N) out[i] = b[i];
}

// ---------------------------------------------------------------------------
extern "C" void kernel_launch(void* const* d_in, const int* in_sizes, int n_in,
                              void* d_out, int out_size) {
    const float* At = (const float*)d_in[0];
    const float* b  = (const float*)d_in[1];
    const float* w1 = (const float*)d_in[2];
    const float* W2 = (const float*)d_in[3];
    int N = in_sizes[1];                 // 20000
    int NC = N / L;
    float* out = (float*)d_out;

    const int SMEM_W2 = 32 * D * (int)sizeof(float);   // 128KB
    cudaFuncSetAttribute(k_w2, cudaFuncAttributeMaxDynamicSharedMemorySize, SMEM_W2);

    dim3 tb(32, 8);
    dim3 tg((N + 31) / 32, D / 32);
    k_transpose<<<tg, tb>>>(At, N);

    k_gram<<<NC, 1024>>>(NC);

    k_dummy<<<1, 1>>>();                 // shifts ncu capture slot onto k_w2

    k_w2<<<128, 128, SMEM_W2>>>(W2, N);  // 512 warps = 512 rows

    k_reduce<<<(N + 255) / 256, 256>>>(N);

    k_w1<<<1, 1024>>>(w1, b, out, N);

    if (out_size >= 2 * N)
        k_copyb<<<(N + 255) / 256, 256>>>(b, out + N, N);
}

// round 11
// speedup vs baseline: 4.7947x; 1.8918x over previous
#include <cuda_runtime.h>

#define ETA 1e-5f
#define FULLMASK 0xffffffffu

static const int D     = 1024;
static const int DA    = 1023;   // a = x[:-1]
static const int NMAX  = 20000;
static const int L     = 32;     // chunk length
static const int NCMAX = NMAX / L;
static const int W2CTAS = 128;   // CTAs doing the W2 path (4 rows each x 128 = 512)

// Static device scratch (no runtime allocation allowed)
__device__ float g_AtT[(size_t)NMAX * D];          // row i = x_i (contiguous)
__device__ float g_last[NMAX];                     // x_i[1023] densely packed
__device__ float g_S[(size_t)NCMAX * L * L];       // per-chunk a-Gram
__device__ float g_Tp[(size_t)NMAX * W2CTAS];      // per-CTA t^2 partials: [i*128 + cta]
__device__ int   g_ready[NCMAX];                   // chunk completion counters
__device__ unsigned long long g_dummy;

// ---------------------------------------------------------------------------
// V8: 32 floats as 8 named float4 members. Lane-interleaved ownership:
// lane l owns float4s {l, l+32, ..., l+224} -> coalesced LDG/LDS.128.
// ---------------------------------------------------------------------------
struct V8 { float4 a, b, c, d, e, f, g, h; };

#define V8_FOREACH(M) M(a) M(b) M(c) M(d) M(e) M(f) M(g) M(h)

__device__ __forceinline__ void ldv8g(V8& v, int row, int lane, bool mask_last) {
    const float4* q = reinterpret_cast<const float4*>(&g_AtT[(size_t)row * D]) + lane;
    v.a = q[0];   v.b = q[32];  v.c = q[64];  v.d = q[96];
    v.e = q[128]; v.f = q[160]; v.g = q[192]; v.h = q[224];
    if (mask_last && lane == 31) v.h.w = 0.f;
}

__device__ __forceinline__ void ldv8s(V8& v, const float* smrow, int lane) {
    const float4* q = reinterpret_cast<const float4*>(smrow) + lane;
    v.a = q[0];   v.b = q[32];  v.c = q[64];  v.d = q[96];
    v.e = q[128]; v.f = q[160]; v.g = q[192]; v.h = q[224];
}

__device__ __forceinline__ float dot32(const V8& u, const V8& v) {
    float s0, s1, s2, s3;
    s0 = u.a.x * v.a.x; s1 = u.a.y * v.a.y; s2 = u.a.z * v.a.z; s3 = u.a.w * v.a.w;
#define DOT_M(m) \
    s0 = fmaf(u.m.x, v.m.x, s0); s1 = fmaf(u.m.y, v.m.y, s1); \
    s2 = fmaf(u.m.z, v.m.z, s2); s3 = fmaf(u.m.w, v.m.w, s3);
    DOT_M(b) DOT_M(c) DOT_M(d) DOT_M(e) DOT_M(f) DOT_M(g) DOT_M(h)
#undef DOT_M
    return (s0 + s1) + (s2 + s3);
}

__device__ __forceinline__ void fma32(V8& G, float t, const V8& x) {
#define FMA_M(m) \
    G.m.x = fmaf(t, x.m.x, G.m.x); G.m.y = fmaf(t, x.m.y, G.m.y); \
    G.m.z = fmaf(t, x.m.z, G.m.z); G.m.w = fmaf(t, x.m.w, G.m.w);
    V8_FOREACH(FMA_M)
#undef FMA_M
}

__device__ __forceinline__ void zero32(V8& G) {
    float4 z = make_float4(0.f, 0.f, 0.f, 0.f);
#define Z_M(m) G.m = z;
    V8_FOREACH(Z_M)
#undef Z_M
}

__device__ __forceinline__ float warp_sum(float s) {
    #pragma unroll
    for (int o = 16; o; o >>= 1) s += __shfl_xor_sync(FULLMASK, s, o);
    return s;
}

// Batched transpose-reduce: 32 reductions in 31 shfl (critical path 5).
__device__ __forceinline__ float colsum32(float (&P)[32], int lane) {
    #pragma unroll
    for (int s = 16; s >= 1; s >>= 1) {
        bool hi = (lane & s) != 0;
        #pragma unroll
        for (int v = 0; v < s; v++) {
            float send = hi ? P[v] : P[v + s];
            float recv = __shfl_xor_sync(FULLMASK, send, s);
            float keep = hi ? P[v + s] : P[v];
            P[v] = keep + recv;
        }
    }
    return P[0];
}

__device__ __forceinline__ int ld_acquire(const int* p) {
    int v;
    asm volatile("ld.acquire.gpu.global.b32 %0, [%1];" : "=r"(v) : "l"(p) : "memory");
    return v;
}

// ---------------------------------------------------------------------------
// Kernel 0: transpose At (D x N) -> g_AtT; pack column 1023.
// ---------------------------------------------------------------------------
__global__ void k_transpose(const float* __restrict__ At, int N) {
    __shared__ float tile[32][33];
    int i0 = blockIdx.x * 32;
    int r0 = blockIdx.y * 32;
    int tx = threadIdx.x, ty = threadIdx.y;   // blockDim (32, 8)
    #pragma unroll
    for (int k = 0; k < 32; k += 8) {
        int r = r0 + ty + k, i = i0 + tx;
        if (i < N) tile[ty + k][tx] = At[(size_t)r * N + i];
    }
    __syncthreads();
    #pragma unroll
    for (int k = 0; k < 32; k += 8) {
        int i = i0 + ty + k, r = r0 + tx;
        if (i < N) {
            float v = tile[tx][ty + k];
            g_AtT[(size_t)i * D + r] = v;
            if (r == D - 1) g_last[i] = v;
        }
    }
}

// ---------------------------------------------------------------------------
// Kernel 0b: per-chunk a-Gram. One CTA (1024 thr) per chunk.
// ---------------------------------------------------------------------------
__global__ void __launch_bounds__(1024) k_gram(int NC) {
    __shared__ float tile[64][33];
    int c = blockIdx.x;
    if (c >= NC) return;
    int tid = threadIdx.x;
    int i = tid & 31, j = tid >> 5;
    int base = c * L;
    float s = 0.f;
    for (int k0 = 0; k0 < D; k0 += 64) {
        __syncthreads();
        #pragma unroll
        for (int e = tid; e < 32 * 64; e += 1024) {
            int row = e >> 6, kk = e & 63;
            tile[kk][row] = g_AtT[(size_t)(base + row) * D + k0 + kk];
        }
        __syncthreads();
        #pragma unroll
        for (int kk = 0; kk < 64; kk++)
            s = fmaf(tile[kk][j], tile[kk][i], s);
    }
    float lj = g_last[base + j];
    float li = g_last[base + i];
    g_S[(size_t)c * (L * L) + j * L + i] = s - lj * li;
}

// ---------------------------------------------------------------------------
// Kernel 0c: zero the chunk-ready counters (needed every graph replay).
// ---------------------------------------------------------------------------
__global__ void k_zero(int NC) {
    int i = blockIdx.x * blockDim.x + threadIdx.x;
    if (i < NC) g_ready[i] = 0;
}

__global__ void k_dummy() { g_dummy = 0ull; }   // ncu capture-slot alignment

// ---------------------------------------------------------------------------
// FUSED persistent kernel: 129 CTAs x 128 threads, all resident (1 CTA/SM).
// CTAs 0..127: W2 path (4 rows each). CTA 128: pipelined w1 scan.
// ---------------------------------------------------------------------------
__global__ void __launch_bounds__(128) k_fused(const float* __restrict__ W2init,
                                               const float* __restrict__ w1init,
                                               const float* __restrict__ b,
                                               float* __restrict__ preds, int N) {
    extern __shared__ float sm[];        // 128KB: w2 tile / w1 state
    __shared__ float sm_t2[4][32];
    __shared__ float sm_p[32];
    __shared__ float sm_c[32];
    __shared__ float sm_T2[32];
    int cta  = blockIdx.x;
    int tid  = threadIdx.x;
    int wix  = tid >> 5;
    int lane = tid & 31;
    int NC   = N / L;

    if (cta < W2CTAS) {
        // ================= W2 role =================
        int r = cta * 4 + wix;           // row 0..511
        V8 G; zero32(G);

        // qinit = W2init[r] . a_0
        float qinit;
        {
            V8 x; ldv8g(x, 0, lane, true);
            const float* wrow = W2init + (size_t)r * DA;
            float s0 = 0.f, s1 = 0.f, s2 = 0.f, s3 = 0.f;
            int eo;
#define QD(m, kk) \
            eo = (kk * 32 + lane) * 4; \
            s0 = fmaf(wrow[eo + 0], x.m.x, s0); \
            s1 = fmaf(wrow[eo + 1], x.m.y, s1); \
            s2 = fmaf(wrow[eo + 2], x.m.z, s2); \
            s3 = fmaf((eo + 3 < DA) ? wrow[eo + 3] : 0.f, x.m.w, s3);
            QD(a,0) QD(b,1) QD(c,2) QD(d,3) QD(e,4) QD(f,5) QD(g,6) QD(h,7)
#undef QD
            qinit = warp_sum((s0 + s1) + (s2 + s3));
        }

        for (int c = 0; c < NC; c++) {
            int base = c * L;

            // Cooperative tile load: 32 rows x 1024 floats.
            {
                const float4* src = reinterpret_cast<const float4*>(&g_AtT[(size_t)base * D]);
                float4* dst = reinterpret_cast<float4*>(sm);
                #pragma unroll
                for (int e = 0; e < 64; e++)
                    dst[tid + 128 * e] = src[tid + 128 * e];
            }
            __syncthreads();
            if (tid < 32) sm[tid * D + (D - 1)] = 0.f;    // mask element 1023
            __syncthreads();

            // Prefetch S column.
            float Scol[32];
            {
                const float* Sc = &g_S[(size_t)c * (L * L)];
                #pragma unroll
                for (int j = 0; j < 32; j++) Scol[j] = Sc[j * 32 + lane];
            }

            // Phase 1: P[i] = lane-partial of (G . a_{base+i})
            float P[32];
            #pragma unroll
            for (int i = 0; i < 32; i++) {
                V8 x; ldv8s(x, sm + i * D, lane);
                P[i] = dot32(G, x);
            }
            float q = colsum32(P, lane);

            // Phase 2: triangular solve. lane i -> t_i.
            bool special = (c == 0) && (lane == 0);
            float acc = 0.f, tfin = 0.f;
            #pragma unroll
            for (int j = 0; j < 32; j++) {
                float cand = fmaf(-2.f * ETA, acc, -ETA * q);
                if (special) cand = qinit;
                float tj = __shfl_sync(FULLMASK, cand, j);
                if (lane == j) tfin = cand;
                acc = fmaf(Scol[j], tj, acc);
            }

            sm_t2[wix][lane] = tfin * tfin;
            __syncthreads();

            // Warp 0 publishes this CTA's t^2 partial, then releases.
            if (wix == 0) {
                float s = (sm_t2[0][lane] + sm_t2[1][lane])
                        + (sm_t2[2][lane] + sm_t2[3][lane]);   // fixed order
                g_Tp[(size_t)(base + lane) * W2CTAS + cta] = s;
                __threadfence();
                atomicAdd(&g_ready[c], 1);                     // 32 per CTA
            }

            // Phase 3: G += sum_i 2 t_i a_i^T
            float t2 = 2.f * tfin;
            #pragma unroll 4
            for (int i = 0; i < 32; i++) {
                float ti2 = __shfl_sync(FULLMASK, t2, i);
                V8 x; ldv8s(x, sm + i * D, lane);
                fma32(G, ti2, x);
            }
            __syncthreads();
        }
    } else {
        // ================= w1 role (1 CTA, pipelined behind W2) =================
        float* sm_g = sm;                 // 1024 floats
        // persistent register copy of owned g slice (8 floats/thread)
        float4 gA = make_float4(0.f, 0.f, 0.f, 0.f), gB = gA;
        {
            float4* gp = reinterpret_cast<float4*>(&sm_g[tid * 8]);
            gp[0] = gA; gp[1] = gB;
        }
        __syncthreads();

        for (int c = 0; c < NC; c++) {
            int base = c * L;

            // Wait for all 128 W2 CTAs (32 releases each) to finish chunk c.
            if (tid == 0) {
                while (ld_acquire(&g_ready[c]) != W2CTAS * 32) __nanosleep(64);
            }
            __syncthreads();

            // T2 reduce: 4 threads per i, fixed-order sums (deterministic).
            {
                int i = tid >> 2, qt = tid & 3;
                const float4* p = reinterpret_cast<const float4*>(
                    &g_Tp[(size_t)(base + i) * W2CTAS + qt * 32]);
                float s0 = 0.f, s1 = 0.f, s2 = 0.f, s3 = 0.f;
                #pragma unroll
                for (int e = 0; e < 8; e++) {
                    float4 v = p[e];
                    s0 += v.x; s1 += v.y; s2 += v.z; s3 += v.w;
                }
                float s = (s0 + s1) + (s2 + s3);
                s += __shfl_xor_sync(FULLMASK, s, 1);
                s += __shfl_xor_sync(FULLMASK, s, 2);
                if (qt == 0) sm_T2[i] = s;
            }

            // Phase A: p_i = x_i . g_s   (rows i = wix*8 + rr)
            #pragma unroll
            for (int rr = 0; rr < 8; rr++) {
                int i = wix * 8 + rr;
                V8 x; ldv8g(x, base + i, lane, false);
                V8 gv;
                if (c == 0 && i == 0) {
                    const float4* wp = reinterpret_cast<const float4*>(w1init) + lane;
                    gv.a = wp[0];   gv.b = wp[32];  gv.c = wp[64];  gv.d = wp[96];
                    gv.e = wp[128]; gv.f = wp[160]; gv.g = wp[192]; gv.h = wp[224];
                } else {
                    ldv8s(gv, sm_g, lane);
                }
                float s = warp_sum(dot32(gv, x));
                if (lane == 0) sm_p[i] = s;
            }
            __syncthreads();

            // Phase B: warp 0 solves the 32-step scalar recurrence.
            if (wix == 0) {
                float p   = sm_p[lane];
                float li  = g_last[base + lane];
                float T2i = sm_T2[lane];
                float bi  = b[base + lane];
                float Scol[32];
                const float* Sc = &g_S[(size_t)c * (L * L)];
                #pragma unroll
                for (int j = 0; j < 32; j++) Scol[j] = Sc[j * 32 + lane];
                bool special = (c == 0) && (lane == 0);
                float acc = 0.f, scal_f = 0.f, c_f = 0.f;
                #pragma unroll
                for (int j = 0; j < 32; j++) {
                    float scal = fmaf(-ETA, p + acc, T2i);
                    if (special) scal = p + T2i;
                    float cc = 2.f * (scal - bi);
                    float lj = __shfl_sync(FULLMASK, li, j);
                    float cj = __shfl_sync(FULLMASK, cc, j);
                    if (lane == j) { scal_f = scal; c_f = cc; }
                    float Sji = fmaf(lj, li, Scol[j]);
                    acc = fmaf(Sji, cj, acc);
                }
                preds[base + lane] = scal_f;
                sm_c[lane] = c_f;
            }
            __syncthreads();

            // Phase C: g[8t..8t+8) += sum_i c_i x_i[8t..8t+8)  (regs + smem mirror)
            {
                #pragma unroll 4
                for (int i = 0; i < 32; i++) {
                    float ci = sm_c[i];
                    const float4* xp = reinterpret_cast<const float4*>(
                        &g_AtT[(size_t)(base + i) * D + tid * 8]);
                    float4 xa = xp[0], xb = xp[1];
                    gA.x = fmaf(ci, xa.x, gA.x); gA.y = fmaf(ci, xa.y, gA.y);
                    gA.z = fmaf(ci, xa.z, gA.z); gA.w = fmaf(ci, xa.w, gA.w);
                    gB.x = fmaf(ci, xb.x, gB.x); gB.y = fmaf(ci, xb.y, gB.y);
                    gB.z = fmaf(ci, xb.z, gB.z); gB.w = fmaf(ci, xb.w, gB.w);
                }
                float4* gp = reinterpret_cast<float4*>(&sm_g[tid * 8]);
                gp[0] = gA; gp[1] = gB;
            }
            __syncthreads();
        }
    }
}

// ---------------------------------------------------------------------------
// Kernel 3: copy b into second half of output
// ---------------------------------------------------------------------------
__global__ void k_copyb(const float* __restrict__ b, float* __restrict__ out, int N) {
    int i = blockIdx.x * blockDim.x + threadIdx.x;
    if (i < N) out[i] = b[i];
}

// ---------------------------------------------------------------------------
extern "C" void kernel_launch(void* const* d_in, const int* in_sizes, int n_in,
                              void* d_out, int out_size) {
    const float* At = (const float*)d_in[0];
    const float* b  = (const float*)d_in[1];
    const float* w1 = (const float*)d_in[2];
    const float* W2 = (const float*)d_in[3];
    int N = in_sizes[1];                 // 20000
    int NC = N / L;
    float* out = (float*)d_out;

    const int SMEM = 32 * D * (int)sizeof(float);   // 128KB
    cudaFuncSetAttribute(k_fused, cudaFuncAttributeMaxDynamicSharedMemorySize, SMEM);

    dim3 tb(32, 8);
    dim3 tg((N + 31) / 32, D / 32);
    k_transpose<<<tg, tb>>>(At, N);

    k_gram<<<NC, 1024>>>(NC);

    k_zero<<<(NC + 255) / 256, 256>>>(NC);

    k_dummy<<<1, 1>>>();
    k_dummy<<<1, 1>>>();                 // capture slot (-s 5) -> k_fused

    k_fused<<<W2CTAS + 1, 128, SMEM>>>(W2, w1, b, out, N);

    if (out_size >= 2 * N)
        k_copyb<<<(N + 255) / 256, 256>>>(b, out + N, N);
}

// round 14
// speedup vs baseline: 5.8115x; 1.2121x over previous
#include <cuda_runtime.h>

#define ETA 1e-5f
#define FULLMASK 0xffffffffu

typedef unsigned int u32;

static const int D     = 1024;
static const int DA    = 1023;   // a = x[:-1]
static const int NMAX  = 20000;
static const int L     = 32;     // chunk length
static const int NCMAX = NMAX / L;
static const int W2CTAS = 128;   // CTAs doing the W2 path (4 rows each x 128 = 512)

// Static device scratch (no runtime allocation allowed)
__device__ float g_AtT[(size_t)NMAX * D];          // row i = x_i (contiguous)
__device__ float g_last[NMAX];                     // x_i[1023] densely packed
__device__ float g_S[(size_t)NCMAX * L * L];       // per-chunk a-Gram (symmetric)
__device__ float g_Tp[(size_t)NMAX * W2CTAS];      // per-CTA t^2 partials: [i*128 + cta]
__device__ int   g_ready[NCMAX];                   // chunk completion counters

// ---------------------------------------------------------------------------
// V8: 32 floats as 8 named float4 members. Lane-interleaved ownership:
// lane l owns float4s {l, l+32, ..., l+224} -> coalesced LDG/LDS.128.
// ---------------------------------------------------------------------------
struct V8 { float4 a, b, c, d, e, f, g, h; };

#define V8_FOREACH(M) M(a) M(b) M(c) M(d) M(e) M(f) M(g) M(h)

__device__ __forceinline__ void ldv8g(V8& v, int row, int lane, bool mask_last) {
    const float4* q = reinterpret_cast<const float4*>(&g_AtT[(size_t)row * D]) + lane;
    v.a = q[0];   v.b = q[32];  v.c = q[64];  v.d = q[96];
    v.e = q[128]; v.f = q[160]; v.g = q[192]; v.h = q[224];
    if (mask_last && lane == 31) v.h.w = 0.f;
}

// Shared-memory row load, ALWAYS masks element 1023 (a-dots only).
__device__ __forceinline__ void ldv8sm(V8& v, const float* smrow, int lane) {
    const float4* q = reinterpret_cast<const float4*>(smrow) + lane;
    v.a = q[0];   v.b = q[32];  v.c = q[64];  v.d = q[96];
    v.e = q[128]; v.f = q[160]; v.g = q[192]; v.h = q[224];
    if (lane == 31) v.h.w = 0.f;
}

__device__ __forceinline__ void ldv8s(V8& v, const float* smrow, int lane) {
    const float4* q = reinterpret_cast<const float4*>(smrow) + lane;
    v.a = q[0];   v.b = q[32];  v.c = q[64];  v.d = q[96];
    v.e = q[128]; v.f = q[160]; v.g = q[192]; v.h = q[224];
}

__device__ __forceinline__ float dot32(const V8& u, const V8& v) {
    float s0, s1, s2, s3;
    s0 = u.a.x * v.a.x; s1 = u.a.y * v.a.y; s2 = u.a.z * v.a.z; s3 = u.a.w * v.a.w;
#define DOT_M(m) \
    s0 = fmaf(u.m.x, v.m.x, s0); s1 = fmaf(u.m.y, v.m.y, s1); \
    s2 = fmaf(u.m.z, v.m.z, s2); s3 = fmaf(u.m.w, v.m.w, s3);
    DOT_M(b) DOT_M(c) DOT_M(d) DOT_M(e) DOT_M(f) DOT_M(g) DOT_M(h)
#undef DOT_M
    return (s0 + s1) + (s2 + s3);
}

__device__ __forceinline__ void fma32(V8& G, float t, const V8& x) {
#define FMA_M(m) \
    G.m.x = fmaf(t, x.m.x, G.m.x); G.m.y = fmaf(t, x.m.y, G.m.y); \
    G.m.z = fmaf(t, x.m.z, G.m.z); G.m.w = fmaf(t, x.m.w, G.m.w);
    V8_FOREACH(FMA_M)
#undef FMA_M
}

__device__ __forceinline__ void zero32(V8& G) {
    float4 z = make_float4(0.f, 0.f, 0.f, 0.f);
#define Z_M(m) G.m = z;
    V8_FOREACH(Z_M)
#undef Z_M
}

__device__ __forceinline__ float warp_sum(float s) {
    #pragma unroll
    for (int o = 16; o; o >>= 1) s += __shfl_xor_sync(FULLMASK, s, o);
    return s;
}

__device__ __forceinline__ int ld_acquire(const int* p) {
    int v;
    asm volatile("ld.acquire.gpu.global.b32 %0, [%1];" : "=r"(v) : "l"(p) : "memory");
    return v;
}

__device__ __forceinline__ u32 smem_u32(const void* p) {
    u32 r;
    asm("{ .reg .u64 t; cvta.to.shared.u64 t, %1; cvt.u32.u64 %0, t; }" : "=r"(r) : "l"(p));
    return r;
}

#define CP_ASYNC16(dst_u32, src_ptr) \
    asm volatile("cp.async.cg.shared.global [%0], [%1], 16;" :: "r"(dst_u32), "l"(src_ptr))
#define CP_COMMIT()  asm volatile("cp.async.commit_group;" ::: "memory")
#define CP_WAIT1()   asm volatile("cp.async.wait_group 1;"  ::: "memory")

// ---------------------------------------------------------------------------
// Kernel 0: transpose At (D x N) -> g_AtT; pack column 1023.
// ---------------------------------------------------------------------------
__global__ void k_transpose(const float* __restrict__ At, int N) {
    __shared__ float tile[32][33];
    int i0 = blockIdx.x * 32;
    int r0 = blockIdx.y * 32;
    int tx = threadIdx.x, ty = threadIdx.y;   // blockDim (32, 8)
    #pragma unroll
    for (int k = 0; k < 32; k += 8) {
        int r = r0 + ty + k, i = i0 + tx;
        if (i < N) tile[ty + k][tx] = At[(size_t)r * N + i];
    }
    __syncthreads();
    #pragma unroll
    for (int k = 0; k < 32; k += 8) {
        int i = i0 + ty + k, r = r0 + tx;
        if (i < N) {
            float v = tile[tx][ty + k];
            g_AtT[(size_t)i * D + r] = v;
            if (r == D - 1) g_last[i] = v;
        }
    }
}

// ---------------------------------------------------------------------------
// Kernel 0b: per-chunk a-Gram (symmetric). One CTA (1024 thr) per chunk.
// ---------------------------------------------------------------------------
__global__ void __launch_bounds__(1024) k_gram(int NC) {
    __shared__ float tile[64][33];
    int c = blockIdx.x;
    if (c >= NC) return;
    int tid = threadIdx.x;
    int i = tid & 31, j = tid >> 5;
    int base = c * L;
    float s = 0.f;
    for (int k0 = 0; k0 < D; k0 += 64) {
        __syncthreads();
        #pragma unroll
        for (int e = tid; e < 32 * 64; e += 1024) {
            int row = e >> 6, kk = e & 63;
            tile[kk][row] = g_AtT[(size_t)(base + row) * D + k0 + kk];
        }
        __syncthreads();
        #pragma unroll
        for (int kk = 0; kk < 64; kk++)
            s = fmaf(tile[kk][j], tile[kk][i], s);
    }
    float lj = g_last[base + j];
    float li = g_last[base + i];
    g_S[(size_t)c * (L * L) + j * L + i] = s - lj * li;
}

// ---------------------------------------------------------------------------
// Kernel 0c: zero the chunk-ready counters (every graph replay).
// ---------------------------------------------------------------------------
__global__ void k_zero(int NC) {
    int i = blockIdx.x * blockDim.x + threadIdx.x;
    if (i < NC) g_ready[i] = 0;
}

// ---------------------------------------------------------------------------
// FUSED persistent kernel: 129 CTAs x 128 threads (1 CTA/SM, single wave).
// CTAs 0..127: W2 path, single-pass sub-block scheme + cp.async half-tiles.
// CTA 128: pipelined w1 scan.
// ---------------------------------------------------------------------------
__global__ void __launch_bounds__(128, 1)
k_fused(const float* __restrict__ W2init, const float* __restrict__ w1init,
        const float* __restrict__ b, float* __restrict__ preds, int N) {
    extern __shared__ float sm[];        // 128KB: two 64KB half-tiles / w1 state
    __shared__ float sm_t2[4][32];
    __shared__ float sm_p[32];
    __shared__ float sm_c[32];
    __shared__ float sm_T2[32];
    int cta  = blockIdx.x;
    int tid  = threadIdx.x;
    int wix  = tid >> 5;
    int lane = tid & 31;
    int NC   = N / L;

    if (cta < W2CTAS) {
        // ================= W2 role =================
        int r = cta * 4 + wix;           // G row 0..511
        V8 G; zero32(G);
        u32 smb = smem_u32(sm);

        // qinit = W2init[r] . a_0
        float qinit;
        {
            V8 x; ldv8g(x, 0, lane, true);
            const float* wrow = W2init + (size_t)r * DA;
            float s0 = 0.f, s1 = 0.f, s2 = 0.f, s3 = 0.f;
            int eo;
#define QD(m, kk) \
            eo = (kk * 32 + lane) * 4; \
            s0 = fmaf(wrow[eo + 0], x.m.x, s0); \
            s1 = fmaf(wrow[eo + 1], x.m.y, s1); \
            s2 = fmaf(wrow[eo + 2], x.m.z, s2); \
            s3 = fmaf((eo + 3 < DA) ? wrow[eo + 3] : 0.f, x.m.w, s3);
            QD(a,0) QD(b,1) QD(c,2) QD(d,3) QD(e,4) QD(f,5) QD(g,6) QD(h,7)
#undef QD
            qinit = warp_sum((s0 + s1) + (s2 + s3));
        }

        // ---- cp.async half-tile issue: 64KB = 4096 x 16B, 32 per thread.
        auto issue_half = [&](int chunk, int half) {
            const char* src = (const char*)&g_AtT[(size_t)(chunk * L + half * 16) * D];
            u32 dst = smb + half * 65536u;
            #pragma unroll
            for (int e = 0; e < 32; e++)
                CP_ASYNC16(dst + (tid + 128 * e) * 16u, src + (size_t)(tid + 128 * e) * 16);
            CP_COMMIT();
        };

        // Prologue: both halves of chunk 0 in flight; wait half0.
        issue_half(0, 0);
        issue_half(0, 1);
        CP_WAIT1();
        __syncthreads();

        for (int c = 0; c < NC; c++) {
            const float* Sc = &g_S[(size_t)c * (L * L)];
            float t2keep = 0.f;
            int cn = (c + 1 < NC) ? c + 1 : c;

            // ---- process one half (4 sub-blocks of 4 rows), single tile pass
            #pragma unroll 1
            for (int half = 0; half < 2; half++) {
                const float* smh = sm + half * 16384;
                #pragma unroll 1
                for (int blk = 0; blk < 4; blk++) {
                    int r0 = half * 16 + blk * 4;     // chunk-row of first in block
                    // prefetch S diag-block entries (broadcast; symmetric gram)
                    float s01 = __ldg(Sc + (r0+0) * 32 + (r0+1));
                    float s02 = __ldg(Sc + (r0+0) * 32 + (r0+2));
                    float s03 = __ldg(Sc + (r0+0) * 32 + (r0+3));
                    float s12 = __ldg(Sc + (r0+1) * 32 + (r0+2));
                    float s13 = __ldg(Sc + (r0+1) * 32 + (r0+3));
                    float s23 = __ldg(Sc + (r0+2) * 32 + (r0+3));

                    V8 x0, x1, x2, x3;
                    ldv8sm(x0, smh + (blk*4+0) * D, lane);
                    ldv8sm(x1, smh + (blk*4+1) * D, lane);
                    ldv8sm(x2, smh + (blk*4+2) * D, lane);
                    ldv8sm(x3, smh + (blk*4+3) * D, lane);

                    float q0 = warp_sum(dot32(G, x0));
                    float q1 = warp_sum(dot32(G, x1));
                    float q2 = warp_sum(dot32(G, x2));
                    float q3 = warp_sum(dot32(G, x3));

                    // 4-step scalar solve (all lanes replicated)
                    float t0 = -ETA * q0;
                    if (c == 0 && r0 == 0) t0 = qinit;
                    float t1 = fmaf(-2.f*ETA*s01, t0, -ETA * q1);
                    float t2v = -ETA * q2 - 2.f*ETA * (fmaf(s02, t0, s12 * t1));
                    float t3v = -ETA * q3 - 2.f*ETA * (fmaf(s03, t0, fmaf(s13, t1, s23 * t2v)));

                    if (lane == r0 + 0) t2keep = t0 * t0;
                    if (lane == r0 + 1) t2keep = t1 * t1;
                    if (lane == r0 + 2) t2keep = t2v * t2v;
                    if (lane == r0 + 3) t2keep = t3v * t3v;

                    fma32(G, 2.f * t0,  x0);
                    fma32(G, 2.f * t1,  x1);
                    fma32(G, 2.f * t2v, x2);
                    fma32(G, 2.f * t3v, x3);
                }

                if (half == 0) {
                    __syncthreads();           // all warps done with half0
                    issue_half(cn, 0);         // prefetch next chunk's half0
                    CP_WAIT1();                // half1 of current chunk ready
                    __syncthreads();
                }
            }

            // ---- publish t^2 partial for this CTA
            sm_t2[wix][lane] = t2keep;
            __syncthreads();                   // t2 visible + half1 consumed
            issue_half(cn, 1);                 // prefetch next chunk's half1
            if (wix == 0) {
                float s = (sm_t2[0][lane] + sm_t2[1][lane])
                        + (sm_t2[2][lane] + sm_t2[3][lane]);   // fixed order
                g_Tp[(size_t)(c * L + lane) * W2CTAS + cta] = s;
                __threadfence();
                atomicAdd(&g_ready[c], 1);     // 32 arrivals per CTA
            }
            CP_WAIT1();                        // next chunk's half0 ready
            __syncthreads();
        }
    } else {
        // ================= w1 role (1 CTA, pipelined behind W2) =================
        float* sm_g = sm;                 // 1024 floats
        float4 gA = make_float4(0.f, 0.f, 0.f, 0.f), gB = gA;
        {
            float4* gp = reinterpret_cast<float4*>(&sm_g[tid * 8]);
            gp[0] = gA; gp[1] = gB;
        }
        __syncthreads();

        for (int c = 0; c < NC; c++) {
            int base = c * L;

            if (tid == 0) {
                while (ld_acquire(&g_ready[c]) != W2CTAS * 32) __nanosleep(64);
            }
            __syncthreads();

            // T2 reduce: 4 threads per i, fixed-order sums (deterministic).
            {
                int i = tid >> 2, qt = tid & 3;
                const float4* p = reinterpret_cast<const float4*>(
                    &g_Tp[(size_t)(base + i) * W2CTAS + qt * 32]);
                float s0 = 0.f, s1 = 0.f, s2 = 0.f, s3 = 0.f;
                #pragma unroll
                for (int e = 0; e < 8; e++) {
                    float4 v = p[e];
                    s0 += v.x; s1 += v.y; s2 += v.z; s3 += v.w;
                }
                float s = (s0 + s1) + (s2 + s3);
                s += __shfl_xor_sync(FULLMASK, s, 1);
                s += __shfl_xor_sync(FULLMASK, s, 2);
                if (qt == 0) sm_T2[i] = s;
            }

            // Phase A: p_i = x_i . g_s
            #pragma unroll
            for (int rr = 0; rr < 8; rr++) {
                int i = wix * 8 + rr;
                V8 x; ldv8g(x, base + i, lane, false);
                V8 gv;
                if (c == 0 && i == 0) {
                    const float4* wp = reinterpret_cast<const float4*>(w1init) + lane;
                    gv.a = wp[0];   gv.b = wp[32];  gv.c = wp[64];  gv.d = wp[96];
                    gv.e = wp[128]; gv.f = wp[160]; gv.g = wp[192]; gv.h = wp[224];
                } else {
                    ldv8s(gv, sm_g, lane);
                }
                float s = warp_sum(dot32(gv, x));
                if (lane == 0) sm_p[i] = s;
            }
            __syncthreads();

            // Phase B: warp 0 solves the 32-step scalar recurrence.
            if (wix == 0) {
                float p   = sm_p[lane];
                float li  = g_last[base + lane];
                float T2i = sm_T2[lane];
                float bi  = b[base + lane];
                float Scol[32];
                const float* Sc = &g_S[(size_t)c * (L * L)];
                #pragma unroll
                for (int j = 0; j < 32; j++) Scol[j] = Sc[j * 32 + lane];
                bool special = (c == 0) && (lane == 0);
                float acc = 0.f, scal_f = 0.f, c_f = 0.f;
                #pragma unroll
                for (int j = 0; j < 32; j++) {
                    float scal = fmaf(-ETA, p + acc, T2i);
                    if (special) scal = p + T2i;
                    float cc = 2.f * (scal - bi);
                    float lj = __shfl_sync(FULLMASK, li, j);
                    float cj = __shfl_sync(FULLMASK, cc, j);
                    if (lane == j) { scal_f = scal; c_f = cc; }
                    float Sji = fmaf(lj, li, Scol[j]);
                    acc = fmaf(Sji, cj, acc);
                }
                preds[base + lane] = scal_f;
                sm_c[lane] = c_f;
            }
            __syncthreads();

            // Phase C: g[8t..8t+8) += sum_i c_i x_i[8t..8t+8)
            {
                #pragma unroll 4
                for (int i = 0; i < 32; i++) {
                    float ci = sm_c[i];
                    const float4* xp = reinterpret_cast<const float4*>(
                        &g_AtT[(size_t)(base + i) * D + tid * 8]);
                    float4 xa = xp[0], xb = xp[1];
                    gA.x = fmaf(ci, xa.x, gA.x); gA.y = fmaf(ci, xa.y, gA.y);
                    gA.z = fmaf(ci, xa.z, gA.z); gA.w = fmaf(ci, xa.w, gA.w);
                    gB.x = fmaf(ci, xb.x, gB.x); gB.y = fmaf(ci, xb.y, gB.y);
                    gB.z = fmaf(ci, xb.z, gB.z); gB.w = fmaf(ci, xb.w, gB.w);
                }
                float4* gp = reinterpret_cast<float4*>(&sm_g[tid * 8]);
                gp[0] = gA; gp[1] = gB;
            }
            __syncthreads();
        }
    }
}

// ---------------------------------------------------------------------------
// Kernel 3: copy b into second half of output
// ---------------------------------------------------------------------------
__global__ void k_copyb(const float* __restrict__ b, float* __restrict__ out, int N) {
    int i = blockIdx.x * blockDim.x + threadIdx.x;
    if (i < N) out[i] = b[i];
}

// ---------------------------------------------------------------------------
extern "C" void kernel_launch(void* const* d_in, const int* in_sizes, int n_in,
                              void* d_out, int out_size) {
    const float* At = (const float*)d_in[0];
    const float* b  = (const float*)d_in[1];
    const float* w1 = (const float*)d_in[2];
    const float* W2 = (const float*)d_in[3];
    int N = in_sizes[1];                 // 20000
    int NC = N / L;
    float* out = (float*)d_out;

    const int SMEM = 32 * D * (int)sizeof(float);   // 128KB
    cudaFuncSetAttribute(k_fused, cudaFuncAttributeMaxDynamicSharedMemorySize, SMEM);

    dim3 tb(32, 8);
    dim3 tg((N + 31) / 32, D / 32);
    k_transpose<<<tg, tb>>>(At, N);                 // launch 1

    k_gram<<<NC, 1024>>>(NC);                       // launch 2

    k_zero<<<(NC + 255) / 256, 256>>>(NC);          // launch 3

    k_fused<<<W2CTAS + 1, 128, SMEM>>>(W2, w1, b, out, N);   // launch 4 (ncu slot)

    if (out_size >= 2 * N)
        k_copyb<<<(N + 255) / 256, 256>>>(b, out + N, N);
}

// round 15
// speedup vs baseline: 6.3328x; 1.0897x over previous
#include <cuda_runtime.h>

#define ETA 1e-5f
#define FULLMASK 0xffffffffu

typedef unsigned int u32;

static const int D     = 1024;
static const int DA    = 1023;   // a = x[:-1]
static const int NMAX  = 20000;
static const int L     = 32;     // chunk length
static const int NCMAX = NMAX / L;
static const int W2CTAS = 128;   // CTAs doing the W2 path (4 rows each x 128 = 512)

// Static device scratch (no runtime allocation allowed)
__device__ float g_AtT[(size_t)NMAX * D];          // row i = x_i (contiguous)
__device__ float g_last[NMAX];                     // x_i[1023] densely packed
__device__ float g_S[(size_t)NCMAX * L * L];       // per-chunk a-Gram (symmetric)
__device__ float g_Tp[(size_t)NMAX * W2CTAS];      // per-CTA t^2 partials: [i*128 + cta]
__device__ int   g_ready[NCMAX];                   // chunk completion counters

// ---------------------------------------------------------------------------
// V8: 32 floats as 8 named float4 members. Lane-interleaved ownership:
// lane l owns float4s {l, l+32, ..., l+224} -> coalesced LDG/LDS.128.
// ---------------------------------------------------------------------------
struct V8 { float4 a, b, c, d, e, f, g, h; };

#define V8_FOREACH(M) M(a) M(b) M(c) M(d) M(e) M(f) M(g) M(h)

__device__ __forceinline__ void ldv8g(V8& v, int row, int lane, bool mask_last) {
    const float4* q = reinterpret_cast<const float4*>(&g_AtT[(size_t)row * D]) + lane;
    v.a = q[0];   v.b = q[32];  v.c = q[64];  v.d = q[96];
    v.e = q[128]; v.f = q[160]; v.g = q[192]; v.h = q[224];
    if (mask_last && lane == 31) v.h.w = 0.f;
}

// Shared-memory row load, ALWAYS masks element 1023 (a-dots only).
__device__ __forceinline__ void ldv8sm(V8& v, const float* smrow, int lane) {
    const float4* q = reinterpret_cast<const float4*>(smrow) + lane;
    v.a = q[0];   v.b = q[32];  v.c = q[64];  v.d = q[96];
    v.e = q[128]; v.f = q[160]; v.g = q[192]; v.h = q[224];
    if (lane == 31) v.h.w = 0.f;
}

__device__ __forceinline__ void ldv8s(V8& v, const float* smrow, int lane) {
    const float4* q = reinterpret_cast<const float4*>(smrow) + lane;
    v.a = q[0];   v.b = q[32];  v.c = q[64];  v.d = q[96];
    v.e = q[128]; v.f = q[160]; v.g = q[192]; v.h = q[224];
}

__device__ __forceinline__ float dot32(const V8& u, const V8& v) {
    float s0, s1, s2, s3;
    s0 = u.a.x * v.a.x; s1 = u.a.y * v.a.y; s2 = u.a.z * v.a.z; s3 = u.a.w * v.a.w;
#define DOT_M(m) \
    s0 = fmaf(u.m.x, v.m.x, s0); s1 = fmaf(u.m.y, v.m.y, s1); \
    s2 = fmaf(u.m.z, v.m.z, s2); s3 = fmaf(u.m.w, v.m.w, s3);
    DOT_M(b) DOT_M(c) DOT_M(d) DOT_M(e) DOT_M(f) DOT_M(g) DOT_M(h)
#undef DOT_M
    return (s0 + s1) + (s2 + s3);
}

__device__ __forceinline__ void fma32(V8& G, float t, const V8& x) {
#define FMA_M(m) \
    G.m.x = fmaf(t, x.m.x, G.m.x); G.m.y = fmaf(t, x.m.y, G.m.y); \
    G.m.z = fmaf(t, x.m.z, G.m.z); G.m.w = fmaf(t, x.m.w, G.m.w);
    V8_FOREACH(FMA_M)
#undef FMA_M
}

__device__ __forceinline__ void zero32(V8& G) {
    float4 z = make_float4(0.f, 0.f, 0.f, 0.f);
#define Z_M(m) G.m = z;
    V8_FOREACH(Z_M)
#undef Z_M
}

__device__ __forceinline__ float warp_sum(float s) {
    #pragma unroll
    for (int o = 16; o; o >>= 1) s += __shfl_xor_sync(FULLMASK, s, o);
    return s;
}

__device__ __forceinline__ int ld_acquire(const int* p) {
    int v;
    asm volatile("ld.acquire.gpu.global.b32 %0, [%1];" : "=r"(v) : "l"(p) : "memory");
    return v;
}

__device__ __forceinline__ u32 smem_u32(const void* p) {
    u32 r;
    asm("{ .reg .u64 t; cvta.to.shared.u64 t, %1; cvt.u32.u64 %0, t; }" : "=r"(r) : "l"(p));
    return r;
}

#define CP_ASYNC16(dst_u32, src_ptr) \
    asm volatile("cp.async.cg.shared.global [%0], [%1], 16;" :: "r"(dst_u32), "l"(src_ptr))
#define CP_COMMIT()  asm volatile("cp.async.commit_group;" ::: "memory")
#define CP_WAIT1()   asm volatile("cp.async.wait_group 1;"  ::: "memory")

// ---------------------------------------------------------------------------
// Kernel 0: transpose At (D x N) -> g_AtT; pack column 1023.
// ---------------------------------------------------------------------------
__global__ void k_transpose(const float* __restrict__ At, int N) {
    __shared__ float tile[32][33];
    int i0 = blockIdx.x * 32;
    int r0 = blockIdx.y * 32;
    int tx = threadIdx.x, ty = threadIdx.y;   // blockDim (32, 8)
    #pragma unroll
    for (int k = 0; k < 32; k += 8) {
        int r = r0 + ty + k, i = i0 + tx;
        if (i < N) tile[ty + k][tx] = At[(size_t)r * N + i];
    }
    __syncthreads();
    #pragma unroll
    for (int k = 0; k < 32; k += 8) {
        int i = i0 + ty + k, r = r0 + tx;
        if (i < N) {
            float v = tile[tx][ty + k];
            g_AtT[(size_t)i * D + r] = v;
            if (r == D - 1) g_last[i] = v;
        }
    }
}

// ---------------------------------------------------------------------------
// Kernel 0b: per-chunk a-Gram (symmetric). One CTA (1024 thr) per chunk.
// ---------------------------------------------------------------------------
__global__ void __launch_bounds__(1024) k_gram(int NC) {
    __shared__ float tile[64][33];
    int c = blockIdx.x;
    if (c >= NC) return;
    int tid = threadIdx.x;
    int i = tid & 31, j = tid >> 5;
    int base = c * L;
    float s = 0.f;
    for (int k0 = 0; k0 < D; k0 += 64) {
        __syncthreads();
        #pragma unroll
        for (int e = tid; e < 32 * 64; e += 1024) {
            int row = e >> 6, kk = e & 63;
            tile[kk][row] = g_AtT[(size_t)(base + row) * D + k0 + kk];
        }
        __syncthreads();
        #pragma unroll
        for (int kk = 0; kk < 64; kk++)
            s = fmaf(tile[kk][j], tile[kk][i], s);
    }
    float lj = g_last[base + j];
    float li = g_last[base + i];
    g_S[(size_t)c * (L * L) + j * L + i] = s - lj * li;
}

// ---------------------------------------------------------------------------
// Kernel 0c: zero the chunk-ready counters (every graph replay).
// ---------------------------------------------------------------------------
__global__ void k_zero(int NC) {
    int i = blockIdx.x * blockDim.x + threadIdx.x;
    if (i < NC) g_ready[i] = 0;
}

// ---------------------------------------------------------------------------
// W2 pipelined step for a 2-row block {p0, p0+1}.
// Entering: q0/q1 = TRUE dots of G with rows p0,p0+1; cur0/cur1 = those rows.
// Does: solve -> (if !last) load next rows + raw dots vs pre-update G ->
// update G -> correct raw dots with Gram terms -> q0/q1 for next block.
// ---------------------------------------------------------------------------
__device__ __forceinline__ void w2_step(
    V8& G, V8& cur0, V8& cur1, V8& nxt0, V8& nxt1,
    float& q0, float& q1, float& t2keep,
    const float* smh, const float* Sc, int p0, bool last,
    bool special, float qinit, int lane)
{
    // solve 2x2 block
    float s01 = __ldg(Sc + p0 * 32 + (p0 + 1));
    float t0 = -ETA * q0;
    if (special) t0 = qinit;
    float t1 = fmaf(-2.f * ETA * s01, t0, -ETA * q1);
    if (lane == p0)     t2keep = t0 * t0;
    if (lane == p0 + 1) t2keep = t1 * t1;

    if (!last) {
        int n0 = p0 + 2;
        int lr = (p0 & 15) + 2;              // row within this half-tile
        float sA = __ldg(Sc + p0 * 32 + n0);
        float sB = __ldg(Sc + p0 * 32 + n0 + 1);
        float sC = __ldg(Sc + (p0 + 1) * 32 + n0);
        float sD = __ldg(Sc + (p0 + 1) * 32 + n0 + 1);
        ldv8sm(nxt0, smh + lr * D, lane);
        ldv8sm(nxt1, smh + (lr + 1) * D, lane);
        float r0 = warp_sum(dot32(G, nxt0));     // vs pre-update G
        float r1 = warp_sum(dot32(G, nxt1));
        fma32(G, 2.f * t0, cur0);                // update overlaps shfl chain
        fma32(G, 2.f * t1, cur1);
        q0 = r0 + 2.f * fmaf(t0, sA, t1 * sC);   // Gram correction -> true dots
        q1 = r1 + 2.f * fmaf(t0, sB, t1 * sD);
    } else {
        fma32(G, 2.f * t0, cur0);
        fma32(G, 2.f * t1, cur1);
    }
}

// ---------------------------------------------------------------------------
// FUSED persistent kernel: 129 CTAs x 128 threads (1 CTA/SM, single wave).
// CTAs 0..127: W2 path, pipelined 2-row blocks + cp.async half-tiles.
// CTA 128: pipelined w1 scan.
// ---------------------------------------------------------------------------
__global__ void __launch_bounds__(128, 1)
k_fused(const float* __restrict__ W2init, const float* __restrict__ w1init,
        const float* __restrict__ b, float* __restrict__ preds, int N) {
    extern __shared__ float sm[];        // 128KB: two 64KB half-tiles / w1 state
    __shared__ float sm_t2[4][32];
    __shared__ float sm_p[32];
    __shared__ float sm_c[32];
    __shared__ float sm_T2[32];
    int cta  = blockIdx.x;
    int tid  = threadIdx.x;
    int wix  = tid >> 5;
    int lane = tid & 31;
    int NC   = N / L;

    if (cta < W2CTAS) {
        // ================= W2 role =================
        int r = cta * 4 + wix;           // G row 0..511
        V8 G; zero32(G);
        u32 smb = smem_u32(sm);

        // qinit = W2init[r] . a_0
        float qinit;
        {
            V8 x; ldv8g(x, 0, lane, true);
            const float* wrow = W2init + (size_t)r * DA;
            float s0 = 0.f, s1 = 0.f, s2 = 0.f, s3 = 0.f;
            int eo;
#define QD(m, kk) \
            eo = (kk * 32 + lane) * 4; \
            s0 = fmaf(wrow[eo + 0], x.m.x, s0); \
            s1 = fmaf(wrow[eo + 1], x.m.y, s1); \
            s2 = fmaf(wrow[eo + 2], x.m.z, s2); \
            s3 = fmaf((eo + 3 < DA) ? wrow[eo + 3] : 0.f, x.m.w, s3);
            QD(a,0) QD(b,1) QD(c,2) QD(d,3) QD(e,4) QD(f,5) QD(g,6) QD(h,7)
#undef QD
            qinit = warp_sum((s0 + s1) + (s2 + s3));
        }

        // ---- cp.async half-tile issue: 64KB = 4096 x 16B, 32 per thread.
        auto issue_half = [&](int chunk, int half) {
            const char* src = (const char*)&g_AtT[(size_t)(chunk * L + half * 16) * D];
            u32 dst = smb + half * 65536u;
            #pragma unroll
            for (int e = 0; e < 32; e++)
                CP_ASYNC16(dst + (tid + 128 * e) * 16u, src + (size_t)(tid + 128 * e) * 16);
            CP_COMMIT();
        };

        // Prologue: both halves of chunk 0 in flight; wait half0.
        issue_half(0, 0);
        issue_half(0, 1);
        CP_WAIT1();
        __syncthreads();

        for (int c = 0; c < NC; c++) {
            const float* Sc = &g_S[(size_t)c * (L * L)];
            float t2keep = 0.f;
            int cn = (c + 1 < NC) ? c + 1 : c;

            #pragma unroll 1
            for (int half = 0; half < 2; half++) {
                const float* smh = sm + half * 16384;
                V8 xa0, xa1, xb0, xb1;
                float q0, q1;

                // half prologue: true dots of first block (G is current)
                ldv8sm(xa0, smh + 0 * D, lane);
                ldv8sm(xa1, smh + 1 * D, lane);
                q0 = warp_sum(dot32(G, xa0));
                q1 = warp_sum(dot32(G, xa1));

                int hb = half * 16;
                bool sp0 = (c == 0) && (half == 0);
                #pragma unroll 1
                for (int bb = 0; bb < 4; bb++) {
                    int p0 = hb + 4 * bb;
                    w2_step(G, xa0, xa1, xb0, xb1, q0, q1, t2keep,
                            smh, Sc, p0, false, sp0 && bb == 0, qinit, lane);
                    w2_step(G, xb0, xb1, xa0, xa1, q0, q1, t2keep,
                            smh, Sc, p0 + 2, bb == 3, false, qinit, lane);
                }

                if (half == 0) {
                    __syncthreads();           // all warps done with half0
                    issue_half(cn, 0);         // prefetch next chunk's half0
                    CP_WAIT1();                // half1 of current chunk ready
                    __syncthreads();
                }
            }

            // ---- publish t^2 partial for this CTA
            sm_t2[wix][lane] = t2keep;
            __syncthreads();                   // t2 visible + half1 consumed
            issue_half(cn, 1);                 // prefetch next chunk's half1
            if (wix == 0) {
                float s = (sm_t2[0][lane] + sm_t2[1][lane])
                        + (sm_t2[2][lane] + sm_t2[3][lane]);   // fixed order
                g_Tp[(size_t)(c * L + lane) * W2CTAS + cta] = s;
                __threadfence();
                atomicAdd(&g_ready[c], 1);     // 32 arrivals per CTA
            }
            CP_WAIT1();                        // next chunk's half0 ready
            __syncthreads();
        }
    } else {
        // ================= w1 role (1 CTA, pipelined behind W2) =================
        float* sm_g = sm;                 // 1024 floats
        float4 gA = make_float4(0.f, 0.f, 0.f, 0.f), gB = gA;
        {
            float4* gp = reinterpret_cast<float4*>(&sm_g[tid * 8]);
            gp[0] = gA; gp[1] = gB;
        }
        __syncthreads();

        for (int c = 0; c < NC; c++) {
            int base = c * L;

            if (tid == 0) {
                while (ld_acquire(&g_ready[c]) != W2CTAS * 32) __nanosleep(64);
            }
            __syncthreads();

            // T2 reduce: 4 threads per i, fixed-order sums (deterministic).
            {
                int i = tid >> 2, qt = tid & 3;
                const float4* p = reinterpret_cast<const float4*>(
                    &g_Tp[(size_t)(base + i) * W2CTAS + qt * 32]);
                float s0 = 0.f, s1 = 0.f, s2 = 0.f, s3 = 0.f;
                #pragma unroll
                for (int e = 0; e < 8; e++) {
                    float4 v = p[e];
                    s0 += v.x; s1 += v.y; s2 += v.z; s3 += v.w;
                }
                float s = (s0 + s1) + (s2 + s3);
                s += __shfl_xor_sync(FULLMASK, s, 1);
                s += __shfl_xor_sync(FULLMASK, s, 2);
                if (qt == 0) sm_T2[i] = s;
            }

            // Phase A: p_i = x_i . g_s
            #pragma unroll
            for (int rr = 0; rr < 8; rr++) {
                int i = wix * 8 + rr;
                V8 x; ldv8g(x, base + i, lane, false);
                V8 gv;
                if (c == 0 && i == 0) {
                    const float4* wp = reinterpret_cast<const float4*>(w1init) + lane;
                    gv.a = wp[0];   gv.b = wp[32];  gv.c = wp[64];  gv.d = wp[96];
                    gv.e = wp[128]; gv.f = wp[160]; gv.g = wp[192]; gv.h = wp[224];
                } else {
                    ldv8s(gv, sm_g, lane);
                }
                float s = warp_sum(dot32(gv, x));
                if (lane == 0) sm_p[i] = s;
            }
            __syncthreads();

            // Phase B: warp 0 solves the 32-step scalar recurrence.
            if (wix == 0) {
                float p   = sm_p[lane];
                float li  = g_last[base + lane];
                float T2i = sm_T2[lane];
                float bi  = b[base + lane];
                float Scol[32];
                const float* Sc = &g_S[(size_t)c * (L * L)];
                #pragma unroll
                for (int j = 0; j < 32; j++) Scol[j] = Sc[j * 32 + lane];
                bool special = (c == 0) && (lane == 0);
                float acc = 0.f, scal_f = 0.f, c_f = 0.f;
                #pragma unroll
                for (int j = 0; j < 32; j++) {
                    float scal = fmaf(-ETA, p + acc, T2i);
                    if (special) scal = p + T2i;
                    float cc = 2.f * (scal - bi);
                    float lj = __shfl_sync(FULLMASK, li, j);
                    float cj = __shfl_sync(FULLMASK, cc, j);
                    if (lane == j) { scal_f = scal; c_f = cc; }
                    float Sji = fmaf(lj, li, Scol[j]);
                    acc = fmaf(Sji, cj, acc);
                }
                preds[base + lane] = scal_f;
                sm_c[lane] = c_f;
            }
            __syncthreads();

            // Phase C: g[8t..8t+8) += sum_i c_i x_i[8t..8t+8)
            {
                #pragma unroll 4
                for (int i = 0; i < 32; i++) {
                    float ci = sm_c[i];
                    const float4* xp = reinterpret_cast<const float4*>(
                        &g_AtT[(size_t)(base + i) * D + tid * 8]);
                    float4 xa = xp[0], xb = xp[1];
                    gA.x = fmaf(ci, xa.x, gA.x); gA.y = fmaf(ci, xa.y, gA.y);
                    gA.z = fmaf(ci, xa.z, gA.z); gA.w = fmaf(ci, xa.w, gA.w);
                    gB.x = fmaf(ci, xb.x, gB.x); gB.y = fmaf(ci, xb.y, gB.y);
                    gB.z = fmaf(ci, xb.z, gB.z); gB.w = fmaf(ci, xb.w, gB.w);
                }
                float4* gp = reinterpret_cast<float4*>(&sm_g[tid * 8]);
                gp[0] = gA; gp[1] = gB;
            }
            __syncthreads();
        }
    }
}

// ---------------------------------------------------------------------------
// Kernel 3: copy b into second half of output
// ---------------------------------------------------------------------------
__global__ void k_copyb(const float* __restrict__ b, float* __restrict__ out, int N) {
    int i = blockIdx.x * blockDim.x + threadIdx.x;
    if (i < N) out[i] = b[i];
}

// ---------------------------------------------------------------------------
extern "C" void kernel_launch(void* const* d_in, const int* in_sizes, int n_in,
                              void* d_out, int out_size) {
    const float* At = (const float*)d_in[0];
    const float* b  = (const float*)d_in[1];
    const float* w1 = (const float*)d_in[2];
    const float* W2 = (const float*)d_in[3];
    int N = in_sizes[1];                 // 20000
    int NC = N / L;
    float* out = (float*)d_out;

    const int SMEM = 32 * D * (int)sizeof(float);   // 128KB
    cudaFuncSetAttribute(k_fused, cudaFuncAttributeMaxDynamicSharedMemorySize, SMEM);

    dim3 tb(32, 8);
    dim3 tg((N + 31) / 32, D / 32);
    k_transpose<<<tg, tb>>>(At, N);                 // launch 1

    k_gram<<<NC, 1024>>>(NC);                       // launch 2

    k_zero<<<(NC + 255) / 256, 256>>>(NC);          // launch 3

    k_fused<<<W2CTAS + 1, 128, SMEM>>>(W2, w1, b, out, N);   // launch 4 (ncu slot)

    if (out_size >= 2 * N)
        k_copyb<<<(N + 255) / 256, 256>>>(b, out + N, N);
}